// round 2
// baseline (speedup 1.0000x reference)
#include <cuda_runtime.h>

#define NN      100000
#define NE      400000
#define IN_CHN  1024
#define FC      128
#define OC      3
#define NEG_SLOPE 0.01f

// ---------------- scratch (static device globals; no allocation) ------------
__device__ __align__(16) float g_Yl[(size_t)NN * FC];   // X @ W1_l
__device__ __align__(16) float g_Yr[(size_t)NN * FC];   // X @ W1_r
__device__ __align__(16) float g_S [(size_t)NN * FC];   // segment-sum of Yl
__device__ __align__(16) float g_x1[(size_t)NN * FC];   // layer-1 output
__device__ __align__(16) float g_deg[NN];
__device__ __align__(16) float g_Zl[NN * OC + 4];       // x1 @ W2_l
__device__ __align__(16) float g_Zr[NN * OC + 4];       // x1 @ W2_r
__device__ __align__(16) float g_S2[NN * OC + 4];       // segment-sum of Zl

// ---------------- 0) zero the accumulators ---------------------------------
__global__ void zero_kernel() {
    size_t stride = (size_t)gridDim.x * blockDim.x;
    size_t i = (size_t)blockIdx.x * blockDim.x + threadIdx.x;
    for (size_t j = i; j < (size_t)NN * FC; j += stride) g_S[j] = 0.f;
    for (size_t j = i; j < (size_t)NN;      j += stride) g_deg[j] = 0.f;
    for (size_t j = i; j < (size_t)NN * OC; j += stride) g_S2[j] = 0.f;
}

// ---------------- 1) in-degree (edges are INT32: jax default, no x64) ------
__global__ void deg_kernel(const int* __restrict__ edges) {
    int i = blockIdx.x * blockDim.x + threadIdx.x;
    if (i < NE) {
        int dst = edges[NE + i];
        atomicAdd(&g_deg[dst], 1.0f);
    }
}

// ---------------- 2) SGEMM: Y = X[N,1024] @ W[1024,128] ---------------------
// 128x128 block tile, 16 K-slice, 8x8 per-thread register tile, 256 threads.
// blockIdx.z selects (W1_l -> g_Yl) or (W1_r -> g_Yr).
#define BM 128
#define BN 128
#define BK 16
#define TM 8
#define TN 8

__global__ void __launch_bounds__(256)
sgemm_kernel(const float* __restrict__ A,
             const float* __restrict__ B0, const float* __restrict__ B1,
             int M, int K)
{
    const float* __restrict__ B = blockIdx.z ? B1 : B0;
    float* __restrict__ C = blockIdx.z ? g_Yr : g_Yl;

    __shared__ float As[BK][BM];
    __shared__ float Bs[BK][BN];

    const int tid = threadIdx.x;
    const int tx  = tid & 15;        // 0..15  (N tiles)
    const int ty  = tid >> 4;        // 0..15  (M tiles)
    const int m0  = blockIdx.x * BM;

    // A-tile loader: 128 rows x 16 k; 2 float4 per thread
    const int a_row  = tid >> 2;         // 0..63
    const int a_col4 = (tid & 3) * 4;    // 0,4,8,12
    // B-tile loader: 16 rows x 128 n; 2 float4 per thread
    const int b_row  = tid >> 5;         // 0..7
    const int b_col4 = (tid & 31) * 4;

    float acc[TM][TN];
    #pragma unroll
    for (int i = 0; i < TM; i++)
        #pragma unroll
        for (int j = 0; j < TN; j++) acc[i][j] = 0.f;

    float ar[TM], br[TN];

    for (int k0 = 0; k0 < K; k0 += BK) {
        #pragma unroll
        for (int h = 0; h < 2; h++) {
            int mrow = a_row + h * 64;
            int m = m0 + mrow;
            float4 v = make_float4(0.f, 0.f, 0.f, 0.f);
            if (m < M) v = *(const float4*)(A + (size_t)m * K + k0 + a_col4);
            As[a_col4 + 0][mrow] = v.x;
            As[a_col4 + 1][mrow] = v.y;
            As[a_col4 + 2][mrow] = v.z;
            As[a_col4 + 3][mrow] = v.w;
        }
        #pragma unroll
        for (int h = 0; h < 2; h++) {
            int k = k0 + b_row + h * 8;
            float4 v = *(const float4*)(B + (size_t)k * BN + b_col4);
            *(float4*)&Bs[b_row + h * 8][b_col4] = v;
        }
        __syncthreads();

        #pragma unroll
        for (int k = 0; k < BK; k++) {
            #pragma unroll
            for (int i = 0; i < TM; i++) ar[i] = As[k][ty * TM + i];
            #pragma unroll
            for (int j = 0; j < TN; j++) br[j] = Bs[k][tx * TN + j];
            #pragma unroll
            for (int i = 0; i < TM; i++)
                #pragma unroll
                for (int j = 0; j < TN; j++)
                    acc[i][j] = fmaf(ar[i], br[j], acc[i][j]);
        }
        __syncthreads();
    }

    #pragma unroll
    for (int i = 0; i < TM; i++) {
        int m = m0 + ty * TM + i;
        if (m < M) {
            #pragma unroll
            for (int j = 0; j < TN; j += 4) {
                *(float4*)(C + (size_t)m * BN + tx * TN + j) =
                    make_float4(acc[i][j], acc[i][j+1], acc[i][j+2], acc[i][j+3]);
            }
        }
    }
}

// ---------------- 3) edge aggregation layer 1: S[dst] += Yl[src] -----------
// one warp per edge; lane holds a float4 (32*4 = 128 channels)
__global__ void agg1_kernel(const int* __restrict__ edges) {
    int gtid = blockIdx.x * blockDim.x + threadIdx.x;
    int e    = gtid >> 5;
    int lane = gtid & 31;
    if (e >= NE) return;
    int src = edges[e];
    int dst = edges[NE + e];
    float4 v = ((const float4*)(g_Yl + (size_t)src * FC))[lane];
    float* s = g_S + (size_t)dst * FC + lane * 4;
    atomicAdd(s + 0, v.x);
    atomicAdd(s + 1, v.y);
    atomicAdd(s + 2, v.z);
    atomicAdd(s + 3, v.w);
}

// ---------------- 4) x1 = leaky_relu(S/max(deg,1) + Yr + b1) ----------------
__global__ void finish1_kernel(const float* __restrict__ b1) {
    int i = blockIdx.x * blockDim.x + threadIdx.x;  // float4 index
    if (i >= NN * FC / 4) return;
    int node = i >> 5;        // /32
    int c4   = i & 31;
    float inv = 1.f / fmaxf(g_deg[node], 1.f);
    float4 s  = ((const float4*)g_S)[i];
    float4 yr = ((const float4*)g_Yr)[i];
    float4 b  = ((const float4*)b1)[c4];
    float4 o;
    o.x = s.x * inv + yr.x + b.x;
    o.y = s.y * inv + yr.y + b.y;
    o.z = s.z * inv + yr.z + b.z;
    o.w = s.w * inv + yr.w + b.w;
    o.x = o.x >= 0.f ? o.x : NEG_SLOPE * o.x;
    o.y = o.y >= 0.f ? o.y : NEG_SLOPE * o.y;
    o.z = o.z >= 0.f ? o.z : NEG_SLOPE * o.z;
    o.w = o.w >= 0.f ? o.w : NEG_SLOPE * o.w;
    ((float4*)g_x1)[i] = o;
}

// ---------------- 5) tiny GEMM layer 2: Zl = x1@W2_l, Zr = x1@W2_r ----------
// one warp per node; warp-reduce 3-channel dots
__global__ void gemm2_kernel(const float* __restrict__ W2l,
                             const float* __restrict__ W2r) {
    __shared__ float sWl[FC * OC];
    __shared__ float sWr[FC * OC];
    for (int t = threadIdx.x; t < FC * OC; t += blockDim.x) {
        sWl[t] = W2l[t];
        sWr[t] = W2r[t];
    }
    __syncthreads();

    int gtid = blockIdx.x * blockDim.x + threadIdx.x;
    int node = gtid >> 5;
    int lane = gtid & 31;
    if (node >= NN) return;

    float4 v = ((const float4*)(g_x1 + (size_t)node * FC))[lane];
    float vx[4] = {v.x, v.y, v.z, v.w};
    float al[OC] = {0.f, 0.f, 0.f};
    float arr[OC] = {0.f, 0.f, 0.f};
    #pragma unroll
    for (int u = 0; u < 4; u++) {
        int k = lane * 4 + u;
        #pragma unroll
        for (int c = 0; c < OC; c++) {
            al[c]  = fmaf(vx[u], sWl[k * OC + c], al[c]);
            arr[c] = fmaf(vx[u], sWr[k * OC + c], arr[c]);
        }
    }
    #pragma unroll
    for (int off = 16; off > 0; off >>= 1) {
        #pragma unroll
        for (int c = 0; c < OC; c++) {
            al[c]  += __shfl_xor_sync(0xFFFFFFFFu, al[c],  off);
            arr[c] += __shfl_xor_sync(0xFFFFFFFFu, arr[c], off);
        }
    }
    if (lane == 0) {
        #pragma unroll
        for (int c = 0; c < OC; c++) {
            g_Zl[node * OC + c] = al[c];
            g_Zr[node * OC + c] = arr[c];
        }
    }
}

// ---------------- 6) edge aggregation layer 2 -------------------------------
__global__ void agg2_kernel(const int* __restrict__ edges) {
    int e = blockIdx.x * blockDim.x + threadIdx.x;
    if (e >= NE) return;
    int src = edges[e];
    int dst = edges[NE + e];
    #pragma unroll
    for (int c = 0; c < OC; c++)
        atomicAdd(&g_S2[dst * OC + c], g_Zl[src * OC + c]);
}

// ---------------- 7) out = S2/max(deg,1) + Zr + b2 ---------------------------
__global__ void final_kernel(const float* __restrict__ b2,
                             float* __restrict__ out) {
    int i = blockIdx.x * blockDim.x + threadIdx.x;
    if (i >= NN * OC) return;
    int node = i / OC;
    int c = i - node * OC;
    float inv = 1.f / fmaxf(g_deg[node], 1.f);
    out[i] = g_S2[i] * inv + g_Zr[i] + b2[c];
}

// ---------------- launch -----------------------------------------------------
extern "C" void kernel_launch(void* const* d_in, const int* in_sizes, int n_in,
                              void* d_out, int out_size) {
    const float* features = (const float*)d_in[0];
    const int*   edges2   = (const int*)d_in[2];   // int32! (jax default, no x64)
    const float* W1_l     = (const float*)d_in[5];
    const float* W1_r     = (const float*)d_in[6];
    const float* b1       = (const float*)d_in[7];
    const float* W2_l     = (const float*)d_in[8];
    const float* W2_r     = (const float*)d_in[9];
    const float* b2       = (const float*)d_in[10];
    float*       out      = (float*)d_out;

    zero_kernel<<<2048, 256>>>();
    deg_kernel<<<(NE + 255) / 256, 256>>>(edges2);

    dim3 g1((NN + BM - 1) / BM, 1, 2);
    sgemm_kernel<<<g1, 256>>>(features, W1_l, W1_r, NN, IN_CHN);

    agg1_kernel<<<(NE * 32 + 255) / 256, 256>>>(edges2);
    finish1_kernel<<<(NN * FC / 4 + 255) / 256, 256>>>(b1);
    gemm2_kernel<<<(NN * 32 + 255) / 256, 256>>>(W2_l, W2_r);
    agg2_kernel<<<(NE + 255) / 256, 256>>>(edges2);
    final_kernel<<<(NN * OC + 255) / 256, 256>>>(b2, out);
}

// round 5
// speedup vs baseline: 1.8965x; 1.8965x over previous
#include <cuda_runtime.h>
#include <cstdint>

#define NN      100000
#define NE      400000
#define IN_CHN  1024
#define FC      128
#define OC      3
#define NEG_SLOPE 0.01f

// ---------------- scratch (static device globals; no allocation) ------------
__device__ __align__(16) float g_Yl[(size_t)NN * FC];   // X @ W1_l
__device__ __align__(16) float g_Yr[(size_t)NN * FC];   // X @ W1_r
__device__ __align__(16) float g_S [(size_t)NN * FC];   // segment-sum of Yl
__device__ __align__(16) float g_x1[(size_t)NN * FC];   // layer-1 output
__device__ __align__(16) float g_deg[NN];
__device__ __align__(16) float g_Wt[256 * IN_CHN];      // [Wl|Wr]^T, K-major, tf32
__device__ __align__(16) float g_Zl[NN * OC + 4];
__device__ __align__(16) float g_Zr[NN * OC + 4];
__device__ __align__(16) float g_S2[NN * OC + 4];

__device__ __forceinline__ uint32_t f2tf32(float x) {
    uint32_t r;
    asm("cvt.rna.tf32.f32 %0, %1;" : "=r"(r) : "f"(x));
    return r;
}

// ============ tf32 mma.sync GEMM: Y[:,128] = X[NN,1024] @ Wt_half^T =========
// CTA tile 128M x 128N, BK=32, double-buffered fragment-packed SMEM.
// grid.z = 0 -> g_Yl (Wt rows 0..127), z = 1 -> g_Yr (rows 128..255).
//
// SMEM per buffer:
//   A: [8 mfrag][4 kstep][32 lane][4 floats]  = 16 KB  (m16k8 a-fragments)
//   B: [16 nfrag][4 kstep][32 lane][2 floats] = 16 KB  (k8n8 b-fragments)
#define GBK 32
#define NIT (IN_CHN / GBK)          // 32
#define A_BUF_F 4096
#define B_BUF_F 4096
#define STAGE_F (A_BUF_F + B_BUF_F) // floats per stage
#define GEMM_SMEM (2 * STAGE_F * 4) // 64 KB

__device__ __forceinline__ void mma_tf32(float* c, const uint32_t* a, const uint32_t* b) {
    asm volatile(
        "mma.sync.aligned.m16n8k8.row.col.f32.tf32.tf32.f32 "
        "{%0,%1,%2,%3}, {%4,%5,%6,%7}, {%8,%9}, {%0,%1,%2,%3};"
        : "+f"(c[0]), "+f"(c[1]), "+f"(c[2]), "+f"(c[3])
        : "r"(a[0]), "r"(a[1]), "r"(a[2]), "r"(a[3]), "r"(b[0]), "r"(b[1]));
}

__global__ void __launch_bounds__(256, 2)
gemm1_mma_kernel(const float* __restrict__ A)
{
    extern __shared__ float smf[];
    const int tid = threadIdx.x;
    const int wid = tid >> 5;
    const int lane = tid & 31;
    const int warp_m = wid & 3;          // 0..3 (32 rows each)
    const int warp_n = wid >> 2;         // 0..1 (64 cols each)
    const int m0 = blockIdx.x * 128;
    const int z  = blockIdx.z;
    const float* __restrict__ Bsrc = g_Wt + (size_t)z * 128 * IN_CHN;

    float acc[2][8][4];
    #pragma unroll
    for (int i = 0; i < 2; i++)
        #pragma unroll
        for (int j = 0; j < 8; j++)
            #pragma unroll
            for (int q = 0; q < 4; q++) acc[i][j][q] = 0.f;

    // ---- staging lambda-ish: stage k-chunk `it` into buffer b ----
    // A: e4 in [0,1024): row=e4>>3 (0..127), c4=e4&7 (float4 within 32 k)
    //    mfrag=row>>4, g=row&7, hb=(row>>3)&1, kstep=c4>>1, hi=c4&1
    //    dst = Abuf + ((mfrag*4+kstep)*32 + g*4)*4 + (hb + 2*hi), stride 4/u
    // B: n=e4>>3, nfrag=n>>3, g=n&7; dst = Bbuf + ((nfrag*4+kstep)*32 + g*4)*2 + hi, stride 2/u
    auto stage = [&](int it, float* buf) {
        const int k0 = it * GBK;
        float* Abuf = buf;
        float* Bbuf = buf + A_BUF_F;
        #pragma unroll
        for (int p = 0; p < 4; p++) {
            int e4  = tid + p * 256;
            int row = e4 >> 3, c4 = e4 & 7;
            int kstep = c4 >> 1, hi = c4 & 1;
            // A
            {
                int m = m0 + row;
                float4 v = make_float4(0.f, 0.f, 0.f, 0.f);
                if (m < NN) v = *(const float4*)(A + (size_t)m * IN_CHN + k0 + c4 * 4);
                int mfrag = row >> 4, g = row & 7, hb = (row >> 3) & 1;
                float* d = Abuf + ((mfrag * 4 + kstep) * 32 + g * 4) * 4 + (hb + 2 * hi);
                d[0]  = __uint_as_float(f2tf32(v.x));
                d[4]  = __uint_as_float(f2tf32(v.y));
                d[8]  = __uint_as_float(f2tf32(v.z));
                d[12] = __uint_as_float(f2tf32(v.w));
            }
            // B (already tf32)
            {
                float4 v = *(const float4*)(Bsrc + (size_t)row * IN_CHN + k0 + c4 * 4);
                int nfrag = row >> 3, g = row & 7;
                float* d = Bbuf + ((nfrag * 4 + kstep) * 32 + g * 4) * 2 + hi;
                d[0] = v.x;
                d[2] = v.y;
                d[4] = v.z;
                d[6] = v.w;
            }
        }
    };

    stage(0, smf);
    __syncthreads();

    for (int it = 0; it < NIT; it++) {
        const float* buf = smf + (it & 1) * STAGE_F;
        // compute from buf
        const float* Abuf = buf;
        const float* Bbuf = buf + A_BUF_F;
        #pragma unroll
        for (int ks = 0; ks < 4; ks++) {
            uint32_t a[2][4];
            #pragma unroll
            for (int i = 0; i < 2; i++) {
                const float* p = Abuf + (((warp_m * 2 + i) * 4 + ks) * 32 + lane) * 4;
                float4 v = *(const float4*)p;
                a[i][0] = __float_as_uint(v.x);
                a[i][1] = __float_as_uint(v.y);
                a[i][2] = __float_as_uint(v.z);
                a[i][3] = __float_as_uint(v.w);
            }
            uint32_t b[8][2];
            #pragma unroll
            for (int j = 0; j < 8; j++) {
                const float* p = Bbuf + (((warp_n * 8 + j) * 4 + ks) * 32 + lane) * 2;
                float2 v = *(const float2*)p;
                b[j][0] = __float_as_uint(v.x);
                b[j][1] = __float_as_uint(v.y);
            }
            #pragma unroll
            for (int i = 0; i < 2; i++)
                #pragma unroll
                for (int j = 0; j < 8; j++)
                    mma_tf32(acc[i][j], a[i], b[j]);
        }
        // prefetch next chunk into other buffer (overwrites buffer computed at it-1)
        if (it + 1 < NIT) {
            __syncthreads();          // everyone done reading buf[(it+1)&1] from it-1
            stage(it + 1, smf + ((it + 1) & 1) * STAGE_F);
            __syncthreads();          // next buffer visible before next compute... 
        }
    }

    // ---- epilogue ----
    float* __restrict__ C = z ? g_Yr : g_Yl;
    const int g = lane >> 2, tig = lane & 3;
    #pragma unroll
    for (int i = 0; i < 2; i++) {
        int r0 = m0 + warp_m * 32 + i * 16 + g;
        #pragma unroll
        for (int j = 0; j < 8; j++) {
            int col = warp_n * 64 + j * 8 + tig * 2;
            if (r0 < NN)
                *(float2*)(C + (size_t)r0 * FC + col) = make_float2(acc[i][j][0], acc[i][j][1]);
            if (r0 + 8 < NN)
                *(float2*)(C + (size_t)(r0 + 8) * FC + col) = make_float2(acc[i][j][2], acc[i][j][3]);
        }
    }
}

// ---------------- prep: g_Wt[n][k] = tf32(W[k][n]) ---------------------------
__global__ void prep_wt_kernel(const float* __restrict__ Wl, const float* __restrict__ Wr) {
    int i = blockIdx.x * blockDim.x + threadIdx.x;
    if (i >= 256 * IN_CHN) return;
    int n = i >> 10;
    int k = i & 1023;
    float v = (n < FC) ? Wl[(size_t)k * FC + n] : Wr[(size_t)k * FC + (n - FC)];
    g_Wt[i] = __uint_as_float(f2tf32(v));
}

// ---------------- 0) zero the accumulators ---------------------------------
__global__ void zero_kernel() {
    size_t stride = (size_t)gridDim.x * blockDim.x;
    size_t i = (size_t)blockIdx.x * blockDim.x + threadIdx.x;
    for (size_t j = i; j < (size_t)NN * FC; j += stride) g_S[j] = 0.f;
    for (size_t j = i; j < (size_t)NN;      j += stride) g_deg[j] = 0.f;
    for (size_t j = i; j < (size_t)NN * OC; j += stride) g_S2[j] = 0.f;
}

// ---------------- 1) in-degree ----------------------------------------------
__global__ void deg_kernel(const int* __restrict__ edges) {
    int i = blockIdx.x * blockDim.x + threadIdx.x;
    if (i < NE) atomicAdd(&g_deg[edges[NE + i]], 1.0f);
}

// ---------------- 3) edge aggregation layer 1: S[dst] += Yl[src] -----------
__global__ void agg1_kernel(const int* __restrict__ edges) {
    int gtid = blockIdx.x * blockDim.x + threadIdx.x;
    int e    = gtid >> 5;
    int lane = gtid & 31;
    if (e >= NE) return;
    int src = edges[e];
    int dst = edges[NE + e];
    float4 v = ((const float4*)(g_Yl + (size_t)src * FC))[lane];
    float* s = g_S + (size_t)dst * FC + lane * 4;
    atomicAdd(s + 0, v.x);
    atomicAdd(s + 1, v.y);
    atomicAdd(s + 2, v.z);
    atomicAdd(s + 3, v.w);
}

// ---------------- 4) x1 = leaky_relu(S/max(deg,1) + Yr + b1) ----------------
__global__ void finish1_kernel(const float* __restrict__ b1) {
    int i = blockIdx.x * blockDim.x + threadIdx.x;
    if (i >= NN * FC / 4) return;
    int node = i >> 5;
    int c4   = i & 31;
    float inv = 1.f / fmaxf(g_deg[node], 1.f);
    float4 s  = ((const float4*)g_S)[i];
    float4 yr = ((const float4*)g_Yr)[i];
    float4 b  = ((const float4*)b1)[c4];
    float4 o;
    o.x = s.x * inv + yr.x + b.x;
    o.y = s.y * inv + yr.y + b.y;
    o.z = s.z * inv + yr.z + b.z;
    o.w = s.w * inv + yr.w + b.w;
    o.x = o.x >= 0.f ? o.x : NEG_SLOPE * o.x;
    o.y = o.y >= 0.f ? o.y : NEG_SLOPE * o.y;
    o.z = o.z >= 0.f ? o.z : NEG_SLOPE * o.z;
    o.w = o.w >= 0.f ? o.w : NEG_SLOPE * o.w;
    ((float4*)g_x1)[i] = o;
}

// ---------------- 5) tiny GEMM layer 2 --------------------------------------
__global__ void gemm2_kernel(const float* __restrict__ W2l,
                             const float* __restrict__ W2r) {
    __shared__ float sWl[FC * OC];
    __shared__ float sWr[FC * OC];
    for (int t = threadIdx.x; t < FC * OC; t += blockDim.x) {
        sWl[t] = W2l[t];
        sWr[t] = W2r[t];
    }
    __syncthreads();

    int gtid = blockIdx.x * blockDim.x + threadIdx.x;
    int node = gtid >> 5;
    int lane = gtid & 31;
    if (node >= NN) return;

    float4 v = ((const float4*)(g_x1 + (size_t)node * FC))[lane];
    float vx[4] = {v.x, v.y, v.z, v.w};
    float al[OC] = {0.f, 0.f, 0.f};
    float arr[OC] = {0.f, 0.f, 0.f};
    #pragma unroll
    for (int u = 0; u < 4; u++) {
        int k = lane * 4 + u;
        #pragma unroll
        for (int c = 0; c < OC; c++) {
            al[c]  = fmaf(vx[u], sWl[k * OC + c], al[c]);
            arr[c] = fmaf(vx[u], sWr[k * OC + c], arr[c]);
        }
    }
    #pragma unroll
    for (int off = 16; off > 0; off >>= 1) {
        #pragma unroll
        for (int c = 0; c < OC; c++) {
            al[c]  += __shfl_xor_sync(0xFFFFFFFFu, al[c],  off);
            arr[c] += __shfl_xor_sync(0xFFFFFFFFu, arr[c], off);
        }
    }
    if (lane == 0) {
        #pragma unroll
        for (int c = 0; c < OC; c++) {
            g_Zl[node * OC + c] = al[c];
            g_Zr[node * OC + c] = arr[c];
        }
    }
}

// ---------------- 6) edge aggregation layer 2 -------------------------------
__global__ void agg2_kernel(const int* __restrict__ edges) {
    int e = blockIdx.x * blockDim.x + threadIdx.x;
    if (e >= NE) return;
    int src = edges[e];
    int dst = edges[NE + e];
    #pragma unroll
    for (int c = 0; c < OC; c++)
        atomicAdd(&g_S2[dst * OC + c], g_Zl[src * OC + c]);
}

// ---------------- 7) out = S2/max(deg,1) + Zr + b2 ---------------------------
__global__ void final_kernel(const float* __restrict__ b2,
                             float* __restrict__ out) {
    int i = blockIdx.x * blockDim.x + threadIdx.x;
    if (i >= NN * OC) return;
    int node = i / OC;
    int c = i - node * OC;
    float inv = 1.f / fmaxf(g_deg[node], 1.f);
    out[i] = g_S2[i] * inv + g_Zr[i] + b2[c];
}

// ---------------- launch -----------------------------------------------------
extern "C" void kernel_launch(void* const* d_in, const int* in_sizes, int n_in,
                              void* d_out, int out_size) {
    const float* features = (const float*)d_in[0];
    const int*   edges2   = (const int*)d_in[2];   // int32 (jax default, no x64)
    const float* W1_l     = (const float*)d_in[5];
    const float* W1_r     = (const float*)d_in[6];
    const float* b1       = (const float*)d_in[7];
    const float* W2_l     = (const float*)d_in[8];
    const float* W2_r     = (const float*)d_in[9];
    const float* b2       = (const float*)d_in[10];
    float*       out      = (float*)d_out;

    static bool attr_set = false;
    if (!attr_set) {
        cudaFuncSetAttribute(gemm1_mma_kernel,
                             cudaFuncAttributeMaxDynamicSharedMemorySize, GEMM_SMEM);
        attr_set = true;
    }

    zero_kernel<<<2048, 256>>>();
    deg_kernel<<<(NE + 255) / 256, 256>>>(edges2);
    prep_wt_kernel<<<(256 * IN_CHN + 255) / 256, 256>>>(W1_l, W1_r);

    dim3 g1((NN + 127) / 128, 1, 2);
    gemm1_mma_kernel<<<g1, 256, GEMM_SMEM>>>(features);

    agg1_kernel<<<(NE * 32 + 255) / 256, 256>>>(edges2);
    finish1_kernel<<<(NN * FC / 4 + 255) / 256, 256>>>(b1);
    gemm2_kernel<<<(NN * 32 + 255) / 256, 256>>>(W2_l, W2_r);
    agg2_kernel<<<(NE + 255) / 256, 256>>>(edges2);
    final_kernel<<<(NN * OC + 255) / 256, 256>>>(b2, out);
}